// round 1
// baseline (speedup 1.0000x reference)
#include <cuda_runtime.h>
#include <math.h>

#define BB   64
#define NN   197
#define CC   768
#define HH   12
#define DD   64
#define DICN 1000
#define TOK  (BB*NN)           // 12608
#define QKN  (BB*HH*NN*DD)     // 9,682,944

// ---------------- scratch (static device memory; no allocations) ----------------
__device__ float g_q[QKN];
__device__ float g_k[QKN];
__device__ float g_vz[BB*HH*NN*4];
__device__ float g_zpart[BB*HH*NN*4];
__device__ int   g_idx[TOK];
__device__ float g_M[CC*48];     // per-head Wv^T @ vq_in_w^T, cols = h*4+j
__device__ float g_P[CC*4];      // proj_w @ vq_out_w
__device__ float g_b2[CC];       // proj_w @ vq_out_b + proj_b
__device__ float g_losspart[64];

// ---------------- prep: M[c][h*4+j] = sum_d qkv_w[2C + h*64 + d][c] * vq_in_w[j][h*64+d]
__global__ void prep_m(const float* __restrict__ qkv_w, const float* __restrict__ vq_in_w)
{
    int h = blockIdx.x >> 2, j = blockIdx.x & 3;
    for (int c = threadIdx.x; c < CC; c += blockDim.x) {
        float s = 0.f;
        #pragma unroll 8
        for (int d = 0; d < DD; d++)
            s = fmaf(qkv_w[(size_t)(2*CC + h*DD + d)*CC + c], vq_in_w[j*CC + h*DD + d], s);
        g_M[c*48 + h*4 + j] = s;
    }
}

// ---------------- prep: P[o][j] = sum_c proj_w[o][c]*vq_out_w[c][j]; b2[o] = proj_w[o]·vq_out_b + proj_b[o]
__global__ void prep_p(const float* __restrict__ proj_w, const float* __restrict__ proj_b,
                       const float* __restrict__ vq_out_w, const float* __restrict__ vq_out_b)
{
    int wid = threadIdx.x >> 5, lane = threadIdx.x & 31;
    int o = blockIdx.x * 8 + wid;
    if (o >= CC) return;
    float p0=0.f,p1=0.f,p2=0.f,p3=0.f,bb=0.f;
    for (int c = lane; c < CC; c += 32) {
        float w = proj_w[(size_t)o*CC + c];
        float4 vo = *(const float4*)(vq_out_w + c*4);
        p0 = fmaf(w, vo.x, p0); p1 = fmaf(w, vo.y, p1);
        p2 = fmaf(w, vo.z, p2); p3 = fmaf(w, vo.w, p3);
        bb = fmaf(w, vq_out_b[c], bb);
    }
    #pragma unroll
    for (int off = 16; off; off >>= 1) {
        p0 += __shfl_xor_sync(0xffffffffu, p0, off);
        p1 += __shfl_xor_sync(0xffffffffu, p1, off);
        p2 += __shfl_xor_sync(0xffffffffu, p2, off);
        p3 += __shfl_xor_sync(0xffffffffu, p3, off);
        bb += __shfl_xor_sync(0xffffffffu, bb, off);
    }
    if (lane == 0) {
        *(float4*)(g_P + o*4) = make_float4(p0, p1, p2, p3);
        g_b2[o] = bb + proj_b[o];
    }
}

// ---------------- qk GEMM: [12608,768] @ qkv_w[0:1536]^T -> q (scaled) and k in [B,H,N,D] layout
// 64x64 tile, BK=16, 256 threads, 4x4 per thread, double-buffered smem.
__global__ void __launch_bounds__(256) qk_gemm(const float* __restrict__ X, const float* __restrict__ W)
{
    __shared__ float As[2][16][68];
    __shared__ float Bs[2][16][68];
    int bm = blockIdx.y;           // 0..196
    int bn = blockIdx.x;           // 0..23
    int m0 = bm * 64, c0 = bn * 64;
    int tid = threadIdx.x;
    int tm = tid >> 4, tn = tid & 15;
    int lr = tid >> 2, lk = (tid & 3) * 4;

    const float* Aptr = X + (size_t)(m0 + lr)*CC + lk;
    const float* Bptr = W + (size_t)(c0 + lr)*CC + lk;

    float acc[4][4];
    #pragma unroll
    for (int i = 0; i < 4; i++)
        #pragma unroll
        for (int j = 0; j < 4; j++) acc[i][j] = 0.f;

    float4 ar = *(const float4*)(Aptr);
    float4 br = *(const float4*)(Bptr);
    {
        float* a = (float*)&ar; float* b = (float*)&br;
        #pragma unroll
        for (int i = 0; i < 4; i++) { As[0][lk+i][lr] = a[i]; Bs[0][lk+i][lr] = b[i]; }
    }
    __syncthreads();

    const int nT = CC / 16;  // 48
    for (int t = 0; t < nT; t++) {
        int cur = t & 1, nxt = cur ^ 1;
        if (t + 1 < nT) {
            ar = *(const float4*)(Aptr + (t+1)*16);
            br = *(const float4*)(Bptr + (t+1)*16);
        }
        #pragma unroll
        for (int kk = 0; kk < 16; kk++) {
            float4 a4 = *(const float4*)(&As[cur][kk][tm*4]);
            float4 b4 = *(const float4*)(&Bs[cur][kk][tn*4]);
            float av[4] = {a4.x, a4.y, a4.z, a4.w};
            float bv[4] = {b4.x, b4.y, b4.z, b4.w};
            #pragma unroll
            for (int i = 0; i < 4; i++)
                #pragma unroll
                for (int j = 0; j < 4; j++)
                    acc[i][j] = fmaf(av[i], bv[j], acc[i][j]);
        }
        if (t + 1 < nT) {
            __syncthreads();
            float* a = (float*)&ar; float* b = (float*)&br;
            #pragma unroll
            for (int i = 0; i < 4; i++) { As[nxt][lk+i][lr] = a[i]; Bs[nxt][lk+i][lr] = b[i]; }
            __syncthreads();
        }
    }

    // epilogue: c0 is a multiple of 64 -> whole block column is one head
    int hall = c0 >> 6;                 // 0..23
    bool isq = (hall < HH);
    int hh = isq ? hall : hall - HH;
    float scale = isq ? 0.125f : 1.0f;  // D^-0.5 exactly
    float* dstbase = isq ? g_q : g_k;
    #pragma unroll
    for (int i = 0; i < 4; i++) {
        int m = m0 + tm*4 + i;
        int b = m / NN, n = m % NN;
        float4 o = make_float4(acc[i][0]*scale, acc[i][1]*scale, acc[i][2]*scale, acc[i][3]*scale);
        *(float4*)(dstbase + (((size_t)b*HH + hh)*NN + n)*DD + tn*4) = o;
    }
}

// ---------------- vz GEMM: [12608,768] @ M[768,48] -> g_vz in [B,H,N,4]
__global__ void __launch_bounds__(256) vz_gemm(const float* __restrict__ X)
{
    __shared__ float xs[16][68];
    __shared__ float ms[16][48];
    int m0 = blockIdx.x * 64;
    int tid = threadIdx.x;
    int tm = tid >> 4, tn = tid & 15;
    int lr = tid >> 2, lk = (tid & 3) * 4;
    int mi = tid * 3;
    int mk = mi / 48, mn = mi % 48;

    float acc[4][3];
    #pragma unroll
    for (int i = 0; i < 4; i++)
        #pragma unroll
        for (int j = 0; j < 3; j++) acc[i][j] = 0.f;

    for (int t = 0; t < 48; t++) {
        int k0 = t * 16;
        float4 xv = *(const float4*)(X + (size_t)(m0 + lr)*CC + k0 + lk);
        float m3a = g_M[(k0 + mk)*48 + mn];
        float m3b = g_M[(k0 + mk)*48 + mn + 1];
        float m3c = g_M[(k0 + mk)*48 + mn + 2];
        __syncthreads();
        {
            float* a = (float*)&xv;
            #pragma unroll
            for (int i = 0; i < 4; i++) xs[lk+i][lr] = a[i];
            ms[mk][mn]   = m3a;
            ms[mk][mn+1] = m3b;
            ms[mk][mn+2] = m3c;
        }
        __syncthreads();
        #pragma unroll
        for (int kk = 0; kk < 16; kk++) {
            float4 a4 = *(const float4*)(&xs[kk][tm*4]);
            float av[4] = {a4.x, a4.y, a4.z, a4.w};
            float b0 = ms[kk][tn*3], b1 = ms[kk][tn*3+1], b2 = ms[kk][tn*3+2];
            #pragma unroll
            for (int i = 0; i < 4; i++) {
                acc[i][0] = fmaf(av[i], b0, acc[i][0]);
                acc[i][1] = fmaf(av[i], b1, acc[i][1]);
                acc[i][2] = fmaf(av[i], b2, acc[i][2]);
            }
        }
    }
    #pragma unroll
    for (int i = 0; i < 4; i++) {
        int tok = m0 + tm*4 + i;
        int b = tok / NN, n = tok % NN;
        #pragma unroll
        for (int j = 0; j < 3; j++) {
            int col = tn*3 + j;
            int h = col >> 2, jj = col & 3;
            g_vz[(((size_t)b*HH + h)*NN + n)*4 + jj] = acc[i][j];
        }
    }
}

// ---------------- fused attention: per (b,h): softmax(q k^T) @ vz -> zpart[b,h,n,0:4]
__global__ void __launch_bounds__(256) attn_kernel()
{
    extern __shared__ float sm[];
    float* qs  = sm;                 // 197*68
    float* ks  = sm + 13396;         // 197*68
    float* vzs = sm + 26792;         // 197*4
    int bh = blockIdx.x;
    size_t qb = (size_t)bh * NN * DD;
    int tid = threadIdx.x;

    for (int i4 = tid; i4 < NN*16; i4 += 256) {
        int n = i4 >> 4, dq = i4 & 15;
        *(float4*)(qs + n*68 + dq*4) = *(const float4*)(g_q + qb + (size_t)n*64 + dq*4);
        *(float4*)(ks + n*68 + dq*4) = *(const float4*)(g_k + qb + (size_t)n*64 + dq*4);
    }
    for (int i = tid; i < NN*4; i += 256) vzs[i] = g_vz[(size_t)bh*NN*4 + i];
    __syncthreads();

    int wid = tid >> 5, lane = tid & 31;
    for (int r = wid; r < NN; r += 8) {
        float acc[7];
        #pragma unroll
        for (int jj = 0; jj < 7; jj++) acc[jj] = 0.f;
        const float* qrow = qs + r*68;
        #pragma unroll 4
        for (int d4 = 0; d4 < 16; d4++) {
            float4 qv = *(const float4*)(qrow + d4*4);
            #pragma unroll
            for (int jj = 0; jj < 6; jj++) {
                float4 kv = *(const float4*)(ks + (lane + 32*jj)*68 + d4*4);
                acc[jj] = fmaf(qv.x, kv.x, acc[jj]);
                acc[jj] = fmaf(qv.y, kv.y, acc[jj]);
                acc[jj] = fmaf(qv.z, kv.z, acc[jj]);
                acc[jj] = fmaf(qv.w, kv.w, acc[jj]);
            }
            if (lane < 5) {
                float4 kv = *(const float4*)(ks + (lane + 192)*68 + d4*4);
                acc[6] = fmaf(qv.x, kv.x, acc[6]);
                acc[6] = fmaf(qv.y, kv.y, acc[6]);
                acc[6] = fmaf(qv.z, kv.z, acc[6]);
                acc[6] = fmaf(qv.w, kv.w, acc[6]);
            }
        }
        // row max
        float mx = -1e30f;
        #pragma unroll
        for (int jj = 0; jj < 6; jj++) mx = fmaxf(mx, acc[jj]);
        if (lane < 5) mx = fmaxf(mx, acc[6]);
        #pragma unroll
        for (int off = 16; off; off >>= 1)
            mx = fmaxf(mx, __shfl_xor_sync(0xffffffffu, mx, off));
        // exp + weighted vz
        float s = 0.f, z0 = 0.f, z1 = 0.f, z2 = 0.f, z3 = 0.f;
        #pragma unroll
        for (int jj = 0; jj < 7; jj++) {
            int j = lane + 32*jj;
            if (j < NN) {
                float e = __expf(acc[jj] - mx);
                s += e;
                float4 vv = *(const float4*)(vzs + j*4);
                z0 = fmaf(e, vv.x, z0); z1 = fmaf(e, vv.y, z1);
                z2 = fmaf(e, vv.z, z2); z3 = fmaf(e, vv.w, z3);
            }
        }
        #pragma unroll
        for (int off = 16; off; off >>= 1) {
            s  += __shfl_xor_sync(0xffffffffu, s,  off);
            z0 += __shfl_xor_sync(0xffffffffu, z0, off);
            z1 += __shfl_xor_sync(0xffffffffu, z1, off);
            z2 += __shfl_xor_sync(0xffffffffu, z2, off);
            z3 += __shfl_xor_sync(0xffffffffu, z3, off);
        }
        if (lane == 0) {
            float inv = 1.f / s;
            *(float4*)(g_zpart + ((size_t)bh*NN + r)*4) =
                make_float4(z0*inv, z1*inv, z2*inv, z3*inv);
        }
    }
}

// ---------------- reduce z over heads, argmin over 1000 codes, per-block loss partial
__global__ void __launch_bounds__(256) argmin_kernel(const float* __restrict__ codebook,
                                                     const float* __restrict__ vq_in_b)
{
    __shared__ float4 cbs[DICN];
    __shared__ float  cns[DICN];
    __shared__ float  red[256];
    int tid = threadIdx.x;
    for (int c = tid; c < DICN; c += 256) {
        float4 e = *(const float4*)(codebook + c*4);
        cbs[c] = e;
        cns[c] = e.x*e.x + e.y*e.y + e.z*e.z + e.w*e.w;
    }
    __syncthreads();
    int p = blockIdx.x * 256 + tid;
    float lsum = 0.f;
    if (p < TOK) {
        int b = p / NN, n = p % NN;
        float z0 = vq_in_b[0], z1 = vq_in_b[1], z2 = vq_in_b[2], z3 = vq_in_b[3];
        #pragma unroll
        for (int h = 0; h < HH; h++) {
            float4 zp = *(const float4*)(g_zpart + (((size_t)b*HH + h)*NN + n)*4);
            z0 += zp.x; z1 += zp.y; z2 += zp.z; z3 += zp.w;
        }
        float best = 3.4e38f; int bi = 0;
        for (int c = 0; c < DICN; c++) {
            float4 e = cbs[c];
            float d = cns[c] - 2.f*(z0*e.x + z1*e.y + z2*e.z + z3*e.w);
            if (d < best) { best = d; bi = c; }
        }
        g_idx[p] = bi;
        float4 e = cbs[bi];
        float d0 = e.x - z0, d1 = e.y - z1, d2 = e.z - z2, d3 = e.w - z3;
        lsum = d0*d0 + d1*d1 + d2*d2 + d3*d3;
    }
    red[tid] = lsum;
    __syncthreads();
    for (int st = 128; st; st >>= 1) {
        if (tid < st) red[tid] += red[tid + st];
        __syncthreads();
    }
    if (tid == 0) g_losspart[blockIdx.x] = red[0];
}

// ---------------- gather: out[p, :] = codebook[idx[p]] @ P^T + b2
__global__ void gather_out(const float* __restrict__ codebook, float* __restrict__ out)
{
    int p = blockIdx.x;
    int ci = g_idx[p];
    float4 e = *(const float4*)(codebook + ci*4);
    for (int o = threadIdx.x; o < CC; o += 256) {
        float4 pr = *(const float4*)(g_P + o*4);
        out[(size_t)p*CC + o] =
            fmaf(e.x, pr.x, fmaf(e.y, pr.y, fmaf(e.z, pr.z, fmaf(e.w, pr.w, g_b2[o]))));
    }
}

__global__ void loss_final(float* __restrict__ dst)
{
    float s = 0.f;
    for (int i = threadIdx.x; i < 50; i += 32) s += g_losspart[i];
    #pragma unroll
    for (int off = 16; off; off >>= 1) s += __shfl_xor_sync(0xffffffffu, s, off);
    if (threadIdx.x == 0) dst[0] = 1.25f * s / 50432.0f;
}

// ---------------- launch ----------------
extern "C" void kernel_launch(void* const* d_in, const int* in_sizes, int n_in,
                              void* d_out, int out_size)
{
    const float* x        = (const float*)d_in[0];
    const float* qkv_w    = (const float*)d_in[1];
    const float* proj_w   = (const float*)d_in[2];
    const float* proj_b   = (const float*)d_in[3];
    const float* vq_in_w  = (const float*)d_in[4];
    const float* vq_in_b  = (const float*)d_in[5];
    const float* vq_out_w = (const float*)d_in[6];
    const float* vq_out_b = (const float*)d_in[7];
    const float* codebook = (const float*)d_in[8];
    float* out = (float*)d_out;

    cudaFuncSetAttribute(attn_kernel, cudaFuncAttributeMaxDynamicSharedMemorySize, 110336);

    prep_m<<<48, 256>>>(qkv_w, vq_in_w);
    prep_p<<<96, 256>>>(proj_w, proj_b, vq_out_w, vq_out_b);
    qk_gemm<<<dim3(24, 197), 256>>>(x, qkv_w);
    vz_gemm<<<197, 256>>>(x);
    attn_kernel<<<BB*HH, 256, 110336>>>();
    argmin_kernel<<<50, 256>>>(codebook, vq_in_b);
    gather_out<<<TOK, 256>>>(codebook, out);
    loss_final<<<1, 32>>>(out + (size_t)out_size - 1);
}

// round 2
// speedup vs baseline: 1.5097x; 1.5097x over previous
#include <cuda_runtime.h>
#include <math.h>

#define BB   64
#define NN   197
#define CC   768
#define HH   12
#define DD   64
#define DICN 1000
#define TOK  (BB*NN)           // 12608
#define QKN  (BB*HH*NN*DD)     // 9,682,944

typedef unsigned long long ull;

// ---- packed f32x2 helpers (Blackwell sm_103a) ----
__device__ __forceinline__ void fma2(ull& d, ull a, ull b) {
    asm("fma.rn.f32x2 %0, %1, %2, %0;" : "+l"(d) : "l"(a), "l"(b));
}
__device__ __forceinline__ ull dup2(float x) {
    ull r; asm("mov.b64 %0, {%1, %1};" : "=l"(r) : "f"(x)); return r;
}
__device__ __forceinline__ ull pk2(float x, float y) {
    ull r; asm("mov.b64 %0, {%1, %2};" : "=l"(r) : "f"(x), "f"(y)); return r;
}
__device__ __forceinline__ float2 unpk(ull v) {
    float2 f; asm("mov.b64 {%0, %1}, %2;" : "=f"(f.x), "=f"(f.y) : "l"(v)); return f;
}

// ---------------- scratch (static device memory; no allocations) ----------------
__device__ float g_q[QKN];
__device__ float g_k[QKN];
__device__ float g_vz[BB*HH*NN*4];
__device__ float g_zpart[BB*HH*NN*4];
__device__ int   g_idx[TOK];
__device__ float g_M[CC*48];     // per-head Wv^T @ vq_in_w^T, cols = h*4+j
__device__ float g_P[CC*4];      // proj_w @ vq_out_w
__device__ float g_b2[CC];       // proj_w @ vq_out_b + proj_b
__device__ float g_losspart[64];

// ---------------- prep: M[c][h*4+j] = sum_d qkv_w[2C + h*64 + d][c] * vq_in_w[j][h*64+d]
__global__ void prep_m(const float* __restrict__ qkv_w, const float* __restrict__ vq_in_w)
{
    int h = blockIdx.x >> 2, j = blockIdx.x & 3;
    for (int c = threadIdx.x; c < CC; c += blockDim.x) {
        float s = 0.f;
        #pragma unroll 8
        for (int d = 0; d < DD; d++)
            s = fmaf(qkv_w[(size_t)(2*CC + h*DD + d)*CC + c], vq_in_w[j*CC + h*DD + d], s);
        g_M[c*48 + h*4 + j] = s;
    }
}

// ---------------- prep: P[o][j] = sum_c proj_w[o][c]*vq_out_w[c][j]; b2[o] = proj_w[o]·vq_out_b + proj_b[o]
__global__ void prep_p(const float* __restrict__ proj_w, const float* __restrict__ proj_b,
                       const float* __restrict__ vq_out_w, const float* __restrict__ vq_out_b)
{
    int wid = threadIdx.x >> 5, lane = threadIdx.x & 31;
    int o = blockIdx.x * 8 + wid;
    if (o >= CC) return;
    float p0=0.f,p1=0.f,p2=0.f,p3=0.f,bb=0.f;
    for (int c = lane; c < CC; c += 32) {
        float w = proj_w[(size_t)o*CC + c];
        float4 vo = *(const float4*)(vq_out_w + c*4);
        p0 = fmaf(w, vo.x, p0); p1 = fmaf(w, vo.y, p1);
        p2 = fmaf(w, vo.z, p2); p3 = fmaf(w, vo.w, p3);
        bb = fmaf(w, vq_out_b[c], bb);
    }
    #pragma unroll
    for (int off = 16; off; off >>= 1) {
        p0 += __shfl_xor_sync(0xffffffffu, p0, off);
        p1 += __shfl_xor_sync(0xffffffffu, p1, off);
        p2 += __shfl_xor_sync(0xffffffffu, p2, off);
        p3 += __shfl_xor_sync(0xffffffffu, p3, off);
        bb += __shfl_xor_sync(0xffffffffu, bb, off);
    }
    if (lane == 0) {
        *(float4*)(g_P + o*4) = make_float4(p0, p1, p2, p3);
        g_b2[o] = bb + proj_b[o];
    }
}

// ---------------- qk GEMM v2: [12608,768] @ qkv_w[0:1536]^T with f32x2 packed FMA
// 128x128 tile, BK=16, 256 threads, 8x8 per thread (N-packed f32x2 accumulators).
__global__ void __launch_bounds__(256) qk_gemm(const float* __restrict__ X, const float* __restrict__ W)
{
    __shared__ float As[2][16][132];
    __shared__ float Bs[2][16][132];
    int m0 = blockIdx.y * 128, c0 = blockIdx.x * 128;
    int tid = threadIdx.x;
    int tm = tid >> 4, tn = tid & 15;
    int lr = tid >> 2, lk = (tid & 3) * 4;

    int rowA0 = min(m0 + lr,      TOK - 1);
    int rowA1 = min(m0 + lr + 64, TOK - 1);
    const float* A0 = X + (size_t)rowA0*CC + lk;
    const float* A1 = X + (size_t)rowA1*CC + lk;
    const float* B0 = W + (size_t)(c0 + lr)*CC + lk;
    const float* B1 = W + (size_t)(c0 + lr + 64)*CC + lk;

    ull acc[8][4];
    #pragma unroll
    for (int i = 0; i < 8; i++)
        #pragma unroll
        for (int j = 0; j < 4; j++) acc[i][j] = 0ull;

    float4 a0 = *(const float4*)A0;
    float4 a1 = *(const float4*)A1;
    float4 b0 = *(const float4*)B0;
    float4 b1 = *(const float4*)B1;
    {
        float* pa0=(float*)&a0; float* pa1=(float*)&a1;
        float* pb0=(float*)&b0; float* pb1=(float*)&b1;
        #pragma unroll
        for (int i = 0; i < 4; i++) {
            As[0][lk+i][lr]    = pa0[i];
            As[0][lk+i][lr+64] = pa1[i];
            Bs[0][lk+i][lr]    = pb0[i];
            Bs[0][lk+i][lr+64] = pb1[i];
        }
    }
    __syncthreads();

    const int nT = CC / 16;  // 48
    for (int t = 0; t < nT; t++) {
        int cur = t & 1, nxt = cur ^ 1;
        if (t + 1 < nT) {
            a0 = *(const float4*)(A0 + (t+1)*16);
            a1 = *(const float4*)(A1 + (t+1)*16);
            b0 = *(const float4*)(B0 + (t+1)*16);
            b1 = *(const float4*)(B1 + (t+1)*16);
        }
        #pragma unroll
        for (int kk = 0; kk < 16; kk++) {
            float4 aLo = *(const float4*)(&As[cur][kk][tm*4]);
            float4 aHi = *(const float4*)(&As[cur][kk][tm*4 + 64]);
            float4 bLo = *(const float4*)(&Bs[cur][kk][tn*4]);
            float4 bHi = *(const float4*)(&Bs[cur][kk][tn*4 + 64]);
            ull bp0 = pk2(bLo.x, bLo.y);
            ull bp1 = pk2(bLo.z, bLo.w);
            ull bp2 = pk2(bHi.x, bHi.y);
            ull bp3 = pk2(bHi.z, bHi.w);
            float av[8] = {aLo.x,aLo.y,aLo.z,aLo.w,aHi.x,aHi.y,aHi.z,aHi.w};
            #pragma unroll
            for (int i = 0; i < 8; i++) {
                ull ad = dup2(av[i]);
                fma2(acc[i][0], ad, bp0);
                fma2(acc[i][1], ad, bp1);
                fma2(acc[i][2], ad, bp2);
                fma2(acc[i][3], ad, bp3);
            }
        }
        if (t + 1 < nT) {
            __syncthreads();
            float* pa0=(float*)&a0; float* pa1=(float*)&a1;
            float* pb0=(float*)&b0; float* pb1=(float*)&b1;
            #pragma unroll
            for (int i = 0; i < 4; i++) {
                As[nxt][lk+i][lr]    = pa0[i];
                As[nxt][lk+i][lr+64] = pa1[i];
                Bs[nxt][lk+i][lr]    = pb0[i];
                Bs[nxt][lk+i][lr+64] = pb1[i];
            }
            __syncthreads();
        }
    }

    // epilogue: map cols to (q|k, head, d); rows to (b, n)
    #pragma unroll
    for (int half = 0; half < 2; half++) {
        int csp = c0 + tn*4 + half*64;
        int hall = csp >> 6;
        bool isq = (hall < HH);
        int hh = isq ? hall : hall - HH;
        float scale = isq ? 0.125f : 1.0f;
        float* dst = isq ? g_q : g_k;
        int d0 = csp & 63;
        #pragma unroll
        for (int i = 0; i < 8; i++) {
            int m = m0 + ((i < 4) ? (tm*4 + i) : (64 + tm*4 + i - 4));
            if (m >= TOK) continue;
            float2 p0 = unpk(acc[i][half*2]);
            float2 p1 = unpk(acc[i][half*2 + 1]);
            int b = m / NN, n = m - b*NN;
            *(float4*)(dst + (((size_t)b*HH + hh)*NN + n)*DD + d0) =
                make_float4(p0.x*scale, p0.y*scale, p1.x*scale, p1.y*scale);
        }
    }
}

// ---------------- vz GEMM: [12608,768] @ M[768,48] -> g_vz in [B,H,N,4]; 32-row tiles
__global__ void __launch_bounds__(256) vz_gemm(const float* __restrict__ X)
{
    __shared__ float xs[16][36];
    __shared__ float ms[16][48];
    int m0 = blockIdx.x * 32;
    int tid = threadIdx.x;
    int tm = tid >> 4, tn = tid & 15;     // tm rows*2, tn cols*3
    int lr = tid >> 2, lk = (tid & 3) * 4;
    int mi = tid * 3;
    int mk = mi / 48, mn = mi % 48;

    float acc[2][3];
    #pragma unroll
    for (int i = 0; i < 2; i++)
        #pragma unroll
        for (int j = 0; j < 3; j++) acc[i][j] = 0.f;

    for (int t = 0; t < 48; t++) {
        int k0 = t * 16;
        float4 xv = make_float4(0.f,0.f,0.f,0.f);
        if (tid < 128) xv = *(const float4*)(X + (size_t)(m0 + lr)*CC + k0 + lk);
        float m3a = g_M[(k0 + mk)*48 + mn];
        float m3b = g_M[(k0 + mk)*48 + mn + 1];
        float m3c = g_M[(k0 + mk)*48 + mn + 2];
        __syncthreads();
        if (tid < 128) {
            float* a = (float*)&xv;
            #pragma unroll
            for (int i = 0; i < 4; i++) xs[lk+i][lr] = a[i];
        }
        ms[mk][mn]   = m3a;
        ms[mk][mn+1] = m3b;
        ms[mk][mn+2] = m3c;
        __syncthreads();
        #pragma unroll
        for (int kk = 0; kk < 16; kk++) {
            float a0 = xs[kk][tm*2], a1 = xs[kk][tm*2+1];
            float b0 = ms[kk][tn*3], b1 = ms[kk][tn*3+1], b2 = ms[kk][tn*3+2];
            acc[0][0] = fmaf(a0, b0, acc[0][0]);
            acc[0][1] = fmaf(a0, b1, acc[0][1]);
            acc[0][2] = fmaf(a0, b2, acc[0][2]);
            acc[1][0] = fmaf(a1, b0, acc[1][0]);
            acc[1][1] = fmaf(a1, b1, acc[1][1]);
            acc[1][2] = fmaf(a1, b2, acc[1][2]);
        }
    }
    #pragma unroll
    for (int i = 0; i < 2; i++) {
        int tok = m0 + tm*2 + i;
        int b = tok / NN, n = tok % NN;
        #pragma unroll
        for (int j = 0; j < 3; j++) {
            int col = tn*3 + j;
            int h = col >> 2, jj = col & 3;
            g_vz[(((size_t)b*HH + h)*NN + n)*4 + jj] = acc[i][j];
        }
    }
}

// ---------------- fused attention: per (b,h): softmax(q k^T) @ vz -> zpart[b,h,n,0:4]
// 4 rows per warp-iteration (k smem traffic /4), d-packed f32x2 score accumulation.
__global__ void __launch_bounds__(256) attn_kernel()
{
    extern __shared__ float sm[];
    float* qs  = sm;                 // 197*68
    float* ks  = sm + 13396;         // 197*68
    float* vzs = sm + 26792;         // 197*4
    int bh = blockIdx.x;
    size_t qb = (size_t)bh * NN * DD;
    int tid = threadIdx.x;

    for (int i4 = tid; i4 < NN*16; i4 += 256) {
        int n = i4 >> 4, dq = i4 & 15;
        *(float4*)(qs + n*68 + dq*4) = *(const float4*)(g_q + qb + (size_t)n*64 + dq*4);
        *(float4*)(ks + n*68 + dq*4) = *(const float4*)(g_k + qb + (size_t)n*64 + dq*4);
    }
    for (int i = tid; i < NN*4; i += 256) vzs[i] = g_vz[(size_t)bh*NN*4 + i];
    __syncthreads();

    int wid = tid >> 5, lane = tid & 31;
    for (int r0 = wid*4; r0 < NN; r0 += 32) {
        ull acc[4][7];
        #pragma unroll
        for (int i = 0; i < 4; i++)
            #pragma unroll
            for (int jj = 0; jj < 7; jj++) acc[i][jj] = 0ull;
        int ri[4];
        #pragma unroll
        for (int i = 0; i < 4; i++) ri[i] = min(r0 + i, NN - 1);

        #pragma unroll 2
        for (int d4 = 0; d4 < 16; d4++) {
            ull qp[4][2];
            #pragma unroll
            for (int i = 0; i < 4; i++) {
                float4 qv = *(const float4*)(qs + ri[i]*68 + d4*4);
                qp[i][0] = pk2(qv.x, qv.y);
                qp[i][1] = pk2(qv.z, qv.w);
            }
            #pragma unroll
            for (int jj = 0; jj < 6; jj++) {
                float4 kv = *(const float4*)(ks + (lane + 32*jj)*68 + d4*4);
                ull kp0 = pk2(kv.x, kv.y);
                ull kp1 = pk2(kv.z, kv.w);
                #pragma unroll
                for (int i = 0; i < 4; i++) {
                    fma2(acc[i][jj], qp[i][0], kp0);
                    fma2(acc[i][jj], qp[i][1], kp1);
                }
            }
            if (lane < 5) {
                float4 kv = *(const float4*)(ks + (lane + 192)*68 + d4*4);
                ull kp0 = pk2(kv.x, kv.y);
                ull kp1 = pk2(kv.z, kv.w);
                #pragma unroll
                for (int i = 0; i < 4; i++) {
                    fma2(acc[i][6], qp[i][0], kp0);
                    fma2(acc[i][6], qp[i][1], kp1);
                }
            }
        }

        #pragma unroll
        for (int i = 0; i < 4; i++) {
            if (r0 + i >= NN) break;   // warp-uniform
            float sc[7];
            #pragma unroll
            for (int jj = 0; jj < 6; jj++) {
                float2 f = unpk(acc[i][jj]);
                sc[jj] = f.x + f.y;
            }
            float mx = fmaxf(fmaxf(fmaxf(sc[0], sc[1]), fmaxf(sc[2], sc[3])), fmaxf(sc[4], sc[5]));
            if (lane < 5) {
                float2 f = unpk(acc[i][6]);
                sc[6] = f.x + f.y;
                mx = fmaxf(mx, sc[6]);
            }
            #pragma unroll
            for (int off = 16; off; off >>= 1)
                mx = fmaxf(mx, __shfl_xor_sync(0xffffffffu, mx, off));
            float s = 0.f, z0 = 0.f, z1 = 0.f, z2 = 0.f, z3 = 0.f;
            #pragma unroll
            for (int jj = 0; jj < 7; jj++) {
                int j = lane + 32*jj;
                if (j < NN) {
                    float e = __expf(sc[jj] - mx);
                    s += e;
                    float4 vv = *(const float4*)(vzs + j*4);
                    z0 = fmaf(e, vv.x, z0); z1 = fmaf(e, vv.y, z1);
                    z2 = fmaf(e, vv.z, z2); z3 = fmaf(e, vv.w, z3);
                }
            }
            #pragma unroll
            for (int off = 16; off; off >>= 1) {
                s  += __shfl_xor_sync(0xffffffffu, s,  off);
                z0 += __shfl_xor_sync(0xffffffffu, z0, off);
                z1 += __shfl_xor_sync(0xffffffffu, z1, off);
                z2 += __shfl_xor_sync(0xffffffffu, z2, off);
                z3 += __shfl_xor_sync(0xffffffffu, z3, off);
            }
            if (lane == 0) {
                float inv = 1.f / s;
                *(float4*)(g_zpart + ((size_t)bh*NN + (r0 + i))*4) =
                    make_float4(z0*inv, z1*inv, z2*inv, z3*inv);
            }
        }
    }
}

// ---------------- reduce z over heads, argmin over 1000 codes, per-block loss partial
__global__ void __launch_bounds__(256) argmin_kernel(const float* __restrict__ codebook,
                                                     const float* __restrict__ vq_in_b)
{
    __shared__ float4 cbs[DICN];
    __shared__ float  cns[DICN];
    __shared__ float  red[256];
    int tid = threadIdx.x;
    for (int c = tid; c < DICN; c += 256) {
        float4 e = *(const float4*)(codebook + c*4);
        cbs[c] = e;
        cns[c] = e.x*e.x + e.y*e.y + e.z*e.z + e.w*e.w;
    }
    __syncthreads();
    int p = blockIdx.x * 256 + tid;
    float lsum = 0.f;
    if (p < TOK) {
        int b = p / NN, n = p % NN;
        float z0 = vq_in_b[0], z1 = vq_in_b[1], z2 = vq_in_b[2], z3 = vq_in_b[3];
        #pragma unroll
        for (int h = 0; h < HH; h++) {
            float4 zp = *(const float4*)(g_zpart + (((size_t)b*HH + h)*NN + n)*4);
            z0 += zp.x; z1 += zp.y; z2 += zp.z; z3 += zp.w;
        }
        float best = 3.4e38f; int bi = 0;
        for (int c = 0; c < DICN; c++) {
            float4 e = cbs[c];
            float d = cns[c] - 2.f*(z0*e.x + z1*e.y + z2*e.z + z3*e.w);
            if (d < best) { best = d; bi = c; }
        }
        g_idx[p] = bi;
        float4 e = cbs[bi];
        float d0 = e.x - z0, d1 = e.y - z1, d2 = e.z - z2, d3 = e.w - z3;
        lsum = d0*d0 + d1*d1 + d2*d2 + d3*d3;
    }
    red[tid] = lsum;
    __syncthreads();
    for (int st = 128; st; st >>= 1) {
        if (tid < st) red[tid] += red[tid + st];
        __syncthreads();
    }
    if (tid == 0) g_losspart[blockIdx.x] = red[0];
}

// ---------------- gather: out[p, :] = codebook[idx[p]] @ P^T + b2
__global__ void gather_out(const float* __restrict__ codebook, float* __restrict__ out)
{
    int p = blockIdx.x;
    int ci = g_idx[p];
    float4 e = *(const float4*)(codebook + ci*4);
    for (int o = threadIdx.x; o < CC; o += 256) {
        float4 pr = *(const float4*)(g_P + o*4);
        out[(size_t)p*CC + o] =
            fmaf(e.x, pr.x, fmaf(e.y, pr.y, fmaf(e.z, pr.z, fmaf(e.w, pr.w, g_b2[o]))));
    }
}

__global__ void loss_final(float* __restrict__ dst)
{
    float s = 0.f;
    for (int i = threadIdx.x; i < 50; i += 32) s += g_losspart[i];
    #pragma unroll
    for (int off = 16; off; off >>= 1) s += __shfl_xor_sync(0xffffffffu, s, off);
    if (threadIdx.x == 0) dst[0] = 1.25f * s / 50432.0f;
}

// ---------------- launch ----------------
extern "C" void kernel_launch(void* const* d_in, const int* in_sizes, int n_in,
                              void* d_out, int out_size)
{
    const float* x        = (const float*)d_in[0];
    const float* qkv_w    = (const float*)d_in[1];
    const float* proj_w   = (const float*)d_in[2];
    const float* proj_b   = (const float*)d_in[3];
    const float* vq_in_w  = (const float*)d_in[4];
    const float* vq_in_b  = (const float*)d_in[5];
    const float* vq_out_w = (const float*)d_in[6];
    const float* vq_out_b = (const float*)d_in[7];
    const float* codebook = (const float*)d_in[8];
    float* out = (float*)d_out;

    cudaFuncSetAttribute(attn_kernel, cudaFuncAttributeMaxDynamicSharedMemorySize, 110336);

    prep_m<<<48, 256>>>(qkv_w, vq_in_w);
    prep_p<<<96, 256>>>(proj_w, proj_b, vq_out_w, vq_out_b);
    qk_gemm<<<dim3(12, 99), 256>>>(x, qkv_w);
    vz_gemm<<<394, 256>>>(x);
    attn_kernel<<<BB*HH, 256, 110336>>>();
    argmin_kernel<<<50, 256>>>(codebook, vq_in_b);
    gather_out<<<TOK, 256>>>(codebook, out);
    loss_final<<<1, 32>>>(out + (size_t)out_size - 1);
}

// round 5
// speedup vs baseline: 2.3762x; 1.5739x over previous
#include <cuda_runtime.h>
#include <cuda_bf16.h>
#include <math.h>

#define BB   64
#define NN   197
#define CC   768
#define HH   12
#define DD   64
#define DICN 1000
#define TOK  (BB*NN)           // 12608
#define QKC  1536              // q||k columns

typedef unsigned long long ull;
typedef unsigned int u32;

// ---- packed f32x2 helpers (attn kernel) ----
__device__ __forceinline__ void fma2(ull& d, ull a, ull b) {
    asm("fma.rn.f32x2 %0, %1, %2, %0;" : "+l"(d) : "l"(a), "l"(b));
}
__device__ __forceinline__ ull pk2(float x, float y) {
    ull r; asm("mov.b64 %0, {%1, %2};" : "=l"(r) : "f"(x), "f"(y)); return r;
}
__device__ __forceinline__ float2 unpk(ull v) {
    float2 f; asm("mov.b64 {%0, %1}, %2;" : "=f"(f.x), "=f"(f.y) : "l"(v)); return f;
}

// ---- mma.sync / ldmatrix / cp.async helpers (baseline PTX, sm_80+) ----
__device__ __forceinline__ u32 smem_u32(const void* p) {
    u32 a; asm("{ .reg .u64 t; cvta.to.shared.u64 t, %1; cvt.u32.u64 %0, t; }" : "=r"(a) : "l"(p));
    return a;
}
__device__ __forceinline__ void ldsm4(u32& r0, u32& r1, u32& r2, u32& r3, u32 addr) {
    asm volatile("ldmatrix.sync.aligned.m8n8.x4.shared.b16 {%0,%1,%2,%3}, [%4];"
                 : "=r"(r0), "=r"(r1), "=r"(r2), "=r"(r3) : "r"(addr));
}
__device__ __forceinline__ void mma16816(float* d, const u32* a, u32 b0, u32 b1) {
    asm volatile("mma.sync.aligned.m16n8k16.row.col.f32.bf16.bf16.f32 "
                 "{%0,%1,%2,%3},{%4,%5,%6,%7},{%8,%9},{%0,%1,%2,%3};"
                 : "+f"(d[0]), "+f"(d[1]), "+f"(d[2]), "+f"(d[3])
                 : "r"(a[0]), "r"(a[1]), "r"(a[2]), "r"(a[3]), "r"(b0), "r"(b1));
}
__device__ __forceinline__ void cp16(u32 dst, const void* src) {
    asm volatile("cp.async.cg.shared.global [%0], [%1], 16;" :: "r"(dst), "l"(src) : "memory");
}
__device__ __forceinline__ void cp_commit() {
    asm volatile("cp.async.commit_group;" ::: "memory");
}

// ---------------- scratch ----------------
__device__ __nv_bfloat16 g_xh[TOK*CC];
__device__ __nv_bfloat16 g_xl[TOK*CC];
__device__ __nv_bfloat16 g_wh[QKC*CC];
__device__ __nv_bfloat16 g_wl[QKC*CC];
__device__ float g_qk[(size_t)TOK*QKC];   // q (cols 0..767, scaled) || k (768..1535), [tok][1536]
__device__ float g_vz[BB*HH*NN*4];
__device__ float g_zpart[BB*HH*NN*4];
__device__ int   g_idx[TOK];
__device__ float g_M[CC*48];
__device__ float g_P[CC*4];
__device__ float g_b2[CC];
__device__ float g_losspart[64];

// ---------------- bf16 hi/lo split conversion ----------------
__global__ void conv_split(const float* __restrict__ src, __nv_bfloat16* __restrict__ hi,
                           __nv_bfloat16* __restrict__ lo, int n4)
{
    int i = blockIdx.x * 256 + threadIdx.x;
    if (i >= n4) return;
    float4 v = *(const float4*)(src + (size_t)i*4);
    __nv_bfloat16 h0 = __float2bfloat16(v.x);
    __nv_bfloat16 h1 = __float2bfloat16(v.y);
    __nv_bfloat16 h2 = __float2bfloat16(v.z);
    __nv_bfloat16 h3 = __float2bfloat16(v.w);
    __nv_bfloat16 l0 = __float2bfloat16(v.x - __bfloat162float(h0));
    __nv_bfloat16 l1 = __float2bfloat16(v.y - __bfloat162float(h1));
    __nv_bfloat16 l2 = __float2bfloat16(v.z - __bfloat162float(h2));
    __nv_bfloat16 l3 = __float2bfloat16(v.w - __bfloat162float(h3));
    __nv_bfloat162* hp = (__nv_bfloat162*)(hi + (size_t)i*4);
    __nv_bfloat162* lp = (__nv_bfloat162*)(lo + (size_t)i*4);
    hp[0] = __nv_bfloat162(h0, h1); hp[1] = __nv_bfloat162(h2, h3);
    lp[0] = __nv_bfloat162(l0, l1); lp[1] = __nv_bfloat162(l2, l3);
}

// ---------------- prep kernels ----------------
__global__ void prep_m(const float* __restrict__ qkv_w, const float* __restrict__ vq_in_w)
{
    int h = blockIdx.x >> 2, j = blockIdx.x & 3;
    for (int c = threadIdx.x; c < CC; c += blockDim.x) {
        float s = 0.f;
        #pragma unroll 8
        for (int d = 0; d < DD; d++)
            s = fmaf(qkv_w[(size_t)(2*CC + h*DD + d)*CC + c], vq_in_w[j*CC + h*DD + d], s);
        g_M[c*48 + h*4 + j] = s;
    }
}

__global__ void prep_p(const float* __restrict__ proj_w, const float* __restrict__ proj_b,
                       const float* __restrict__ vq_out_w, const float* __restrict__ vq_out_b)
{
    int wid = threadIdx.x >> 5, lane = threadIdx.x & 31;
    int o = blockIdx.x * 8 + wid;
    if (o >= CC) return;
    float p0=0.f,p1=0.f,p2=0.f,p3=0.f,bb=0.f;
    for (int c = lane; c < CC; c += 32) {
        float w = proj_w[(size_t)o*CC + c];
        float4 vo = *(const float4*)(vq_out_w + c*4);
        p0 = fmaf(w, vo.x, p0); p1 = fmaf(w, vo.y, p1);
        p2 = fmaf(w, vo.z, p2); p3 = fmaf(w, vo.w, p3);
        bb = fmaf(w, vq_out_b[c], bb);
    }
    #pragma unroll
    for (int off = 16; off; off >>= 1) {
        p0 += __shfl_xor_sync(0xffffffffu, p0, off);
        p1 += __shfl_xor_sync(0xffffffffu, p1, off);
        p2 += __shfl_xor_sync(0xffffffffu, p2, off);
        p3 += __shfl_xor_sync(0xffffffffu, p3, off);
        bb += __shfl_xor_sync(0xffffffffu, bb, off);
    }
    if (lane == 0) {
        *(float4*)(g_P + o*4) = make_float4(p0, p1, p2, p3);
        g_b2[o] = bb + proj_b[o];
    }
}

// ---------------- qk GEMM on HMMA (mma.sync m16n8k16 bf16), hi/lo split ----------------
// CTA tile 128(M) x 128(N), warp grid 2x4, warp tile 64x32.
// K chunks of 64 via 2-stage cp.async pipeline; 4 regions (Ah,Al,Bh,Bl) of 16KB per stage.
// smem row = 128 bytes (64 bf16), XOR-swizzled within-row by ((row&7)<<4).
#define STAGE 65536

__global__ void __launch_bounds__(256, 1) qk_mma()
{
    extern __shared__ __align__(128) char smem[];
    u32 sbase = smem_u32(smem);
    int tid = threadIdx.x;
    int wid = tid >> 5, lane = tid & 31;
    int wm = wid & 1, wn = wid >> 1;
    int m0 = blockIdx.y * 128;
    int c0 = blockIdx.x * 128;

    // ldmatrix lane address precompute: row base and swizzle bits SEPARATE;
    // column offset must be XORed with swizzle bits (bits 4-6), never added.
    int q = lane >> 3, lr = lane & 7;
    u32 arow[4], asw[4];
    #pragma unroll
    for (int mf = 0; mf < 4; mf++) {
        int r = wm*64 + mf*16 + ((q & 1) << 3) + lr;
        arow[mf] = (u32)(r * 128);
        asw[mf]  = (u32)((r & 7) << 4);
    }
    u32 akb = (u32)((q >> 1) << 4);   // +16B for k+8 matrices
    u32 brow[2], bsw[2];
    #pragma unroll
    for (int g = 0; g < 2; g++) {
        int nr = wn*32 + g*16 + ((q >> 1) << 3) + lr;
        brow[g] = (u32)(nr * 128);
        bsw[g]  = (u32)((nr & 7) << 4);
    }
    u32 bkb = (u32)((q & 1) << 4);

    float acc[4][4][4];
    #pragma unroll
    for (int a = 0; a < 4; a++)
        #pragma unroll
        for (int b = 0; b < 4; b++)
            #pragma unroll
            for (int c = 0; c < 4; c++) acc[a][b][c] = 0.f;

    // chunk fill via cp.async
    auto fill = [&](int buf, int t) {
        int k0 = t * 64;
        u32 db = sbase + buf*STAGE;
        #pragma unroll
        for (int i = 0; i < 4; i++) {
            int u = i*256 + tid;
            int row = u >> 3, ku = u & 7;
            u32 soff = (u32)(row*128 + ((ku*16) ^ ((row & 7) << 4)));
            int ra = min(m0 + row, TOK - 1);
            size_t aoff = (size_t)ra*CC + k0 + ku*8;
            size_t boff = (size_t)(c0 + row)*CC + k0 + ku*8;
            cp16(db + soff,         g_xh + aoff);
            cp16(db + 16384 + soff, g_xl + aoff);
            cp16(db + 32768 + soff, g_wh + boff);
            cp16(db + 49152 + soff, g_wl + boff);
        }
        cp_commit();
    };

    fill(0, 0);
    for (int t = 0; t < 12; t++) {
        int buf = t & 1;
        if (t + 1 < 12) {
            fill(buf ^ 1, t + 1);
            asm volatile("cp.async.wait_group 1;" ::: "memory");
        } else {
            asm volatile("cp.async.wait_group 0;" ::: "memory");
        }
        __syncthreads();

        u32 Ab  = sbase + buf*STAGE;
        u32 Alb = Ab + 16384;
        u32 Bb  = Ab + 32768;
        u32 Blb = Ab + 49152;
        #pragma unroll
        for (int ks = 0; ks < 4; ks++) {
            u32 kb = (u32)(ks * 32);   // byte offset of k-step within row
            u32 Ah[4][4], Al[4][4], Bh[2][4], Bl[2][4];
            #pragma unroll
            for (int mf = 0; mf < 4; mf++) {
                u32 colA = (kb + akb) ^ asw[mf];
                ldsm4(Ah[mf][0], Ah[mf][1], Ah[mf][2], Ah[mf][3], Ab  + arow[mf] + colA);
                ldsm4(Al[mf][0], Al[mf][1], Al[mf][2], Al[mf][3], Alb + arow[mf] + colA);
            }
            #pragma unroll
            for (int g = 0; g < 2; g++) {
                u32 colB = (kb + bkb) ^ bsw[g];
                ldsm4(Bh[g][0], Bh[g][1], Bh[g][2], Bh[g][3], Bb  + brow[g] + colB);
                ldsm4(Bl[g][0], Bl[g][1], Bl[g][2], Bl[g][3], Blb + brow[g] + colB);
            }
            #pragma unroll
            for (int mf = 0; mf < 4; mf++) {
                #pragma unroll
                for (int g = 0; g < 2; g++) {
                    mma16816(acc[mf][2*g],   Ah[mf], Bh[g][0], Bh[g][1]);
                    mma16816(acc[mf][2*g+1], Ah[mf], Bh[g][2], Bh[g][3]);
                    mma16816(acc[mf][2*g],   Ah[mf], Bl[g][0], Bl[g][1]);
                    mma16816(acc[mf][2*g+1], Ah[mf], Bl[g][2], Bl[g][3]);
                    mma16816(acc[mf][2*g],   Al[mf], Bh[g][0], Bh[g][1]);
                    mma16816(acc[mf][2*g+1], Al[mf], Bh[g][2], Bh[g][3]);
                }
            }
        }
        __syncthreads();
    }

    // epilogue: direct float2 stores to flat g_qk[tok][1536]
    float scale = (c0 < 768) ? 0.125f : 1.0f;
    int rb = m0 + wm*64 + (lane >> 2);
    int nb = c0 + wn*32 + (lane & 3)*2;
    #pragma unroll
    for (int mf = 0; mf < 4; mf++) {
        #pragma unroll
        for (int nf = 0; nf < 4; nf++) {
            int r = rb + mf*16;
            int n = nb + nf*8;
            if (r < TOK)
                *(float2*)(g_qk + (size_t)r*QKC + n) =
                    make_float2(acc[mf][nf][0]*scale, acc[mf][nf][1]*scale);
            if (r + 8 < TOK)
                *(float2*)(g_qk + (size_t)(r+8)*QKC + n) =
                    make_float2(acc[mf][nf][2]*scale, acc[mf][nf][3]*scale);
        }
    }
}

// ---------------- vz GEMM ----------------
__global__ void __launch_bounds__(256) vz_gemm(const float* __restrict__ X)
{
    __shared__ float xs[16][36];
    __shared__ float ms[16][48];
    int m0 = blockIdx.x * 32;
    int tid = threadIdx.x;
    int tm = tid >> 4, tn = tid & 15;
    int lr = tid >> 2, lk = (tid & 3) * 4;
    int mi = tid * 3;
    int mk = mi / 48, mn = mi % 48;

    float acc[2][3];
    #pragma unroll
    for (int i = 0; i < 2; i++)
        #pragma unroll
        for (int j = 0; j < 3; j++) acc[i][j] = 0.f;

    for (int t = 0; t < 48; t++) {
        int k0 = t * 16;
        float4 xv = make_float4(0.f,0.f,0.f,0.f);
        if (tid < 128) xv = *(const float4*)(X + (size_t)(m0 + lr)*CC + k0 + lk);
        float m3a = g_M[(k0 + mk)*48 + mn];
        float m3b = g_M[(k0 + mk)*48 + mn + 1];
        float m3c = g_M[(k0 + mk)*48 + mn + 2];
        __syncthreads();
        if (tid < 128) {
            float* a = (float*)&xv;
            #pragma unroll
            for (int i = 0; i < 4; i++) xs[lk+i][lr] = a[i];
        }
        ms[mk][mn]   = m3a;
        ms[mk][mn+1] = m3b;
        ms[mk][mn+2] = m3c;
        __syncthreads();
        #pragma unroll
        for (int kk = 0; kk < 16; kk++) {
            float a0 = xs[kk][tm*2], a1 = xs[kk][tm*2+1];
            float b0 = ms[kk][tn*3], b1 = ms[kk][tn*3+1], b2 = ms[kk][tn*3+2];
            acc[0][0] = fmaf(a0, b0, acc[0][0]);
            acc[0][1] = fmaf(a0, b1, acc[0][1]);
            acc[0][2] = fmaf(a0, b2, acc[0][2]);
            acc[1][0] = fmaf(a1, b0, acc[1][0]);
            acc[1][1] = fmaf(a1, b1, acc[1][1]);
            acc[1][2] = fmaf(a1, b2, acc[1][2]);
        }
    }
    #pragma unroll
    for (int i = 0; i < 2; i++) {
        int tok = m0 + tm*2 + i;
        int b = tok / NN, n = tok % NN;
        #pragma unroll
        for (int j = 0; j < 3; j++) {
            int col = tn*3 + j;
            int h = col >> 2, jj = col & 3;
            g_vz[(((size_t)b*HH + h)*NN + n)*4 + jj] = acc[i][j];
        }
    }
}

// ---------------- fused attention (reads g_qk flat layout) ----------------
__global__ void __launch_bounds__(256) attn_kernel()
{
    extern __shared__ float sm[];
    float* qs  = sm;                 // 197*68
    float* ks  = sm + 13396;
    float* vzs = sm + 26792;
    int bh = blockIdx.x;
    int b = bh / HH, h = bh % HH;
    const float* qbase = g_qk + (size_t)b*NN*QKC + h*64;
    const float* kbase = qbase + 768;
    int tid = threadIdx.x;

    for (int i4 = tid; i4 < NN*16; i4 += 256) {
        int n = i4 >> 4, dq = i4 & 15;
        *(float4*)(qs + n*68 + dq*4) = *(const float4*)(qbase + (size_t)n*QKC + dq*4);
        *(float4*)(ks + n*68 + dq*4) = *(const float4*)(kbase + (size_t)n*QKC + dq*4);
    }
    for (int i = tid; i < NN*4; i += 256) vzs[i] = g_vz[(size_t)bh*NN*4 + i];
    __syncthreads();

    int wid = tid >> 5, lane = tid & 31;
    for (int r0 = wid*4; r0 < NN; r0 += 32) {
        ull acc[4][7];
        #pragma unroll
        for (int i = 0; i < 4; i++)
            #pragma unroll
            for (int jj = 0; jj < 7; jj++) acc[i][jj] = 0ull;
        int ri[4];
        #pragma unroll
        for (int i = 0; i < 4; i++) ri[i] = min(r0 + i, NN - 1);

        #pragma unroll 2
        for (int d4 = 0; d4 < 16; d4++) {
            ull qp[4][2];
            #pragma unroll
            for (int i = 0; i < 4; i++) {
                float4 qv = *(const float4*)(qs + ri[i]*68 + d4*4);
                qp[i][0] = pk2(qv.x, qv.y);
                qp[i][1] = pk2(qv.z, qv.w);
            }
            #pragma unroll
            for (int jj = 0; jj < 6; jj++) {
                float4 kv = *(const float4*)(ks + (lane + 32*jj)*68 + d4*4);
                ull kp0 = pk2(kv.x, kv.y);
                ull kp1 = pk2(kv.z, kv.w);
                #pragma unroll
                for (int i = 0; i < 4; i++) {
                    fma2(acc[i][jj], qp[i][0], kp0);
                    fma2(acc[i][jj], qp[i][1], kp1);
                }
            }
            if (lane < 5) {
                float4 kv = *(const float4*)(ks + (lane + 192)*68 + d4*4);
                ull kp0 = pk2(kv.x, kv.y);
                ull kp1 = pk2(kv.z, kv.w);
                #pragma unroll
                for (int i = 0; i < 4; i++) {
                    fma2(acc[i][6], qp[i][0], kp0);
                    fma2(acc[i][6], qp[i][1], kp1);
                }
            }
        }

        #pragma unroll
        for (int i = 0; i < 4; i++) {
            if (r0 + i >= NN) break;
            float sc[7];
            #pragma unroll
            for (int jj = 0; jj < 6; jj++) {
                float2 f = unpk(acc[i][jj]);
                sc[jj] = f.x + f.y;
            }
            float mx = fmaxf(fmaxf(fmaxf(sc[0], sc[1]), fmaxf(sc[2], sc[3])), fmaxf(sc[4], sc[5]));
            if (lane < 5) {
                float2 f = unpk(acc[i][6]);
                sc[6] = f.x + f.y;
                mx = fmaxf(mx, sc[6]);
            }
            #pragma unroll
            for (int off = 16; off; off >>= 1)
                mx = fmaxf(mx, __shfl_xor_sync(0xffffffffu, mx, off));
            float s = 0.f, z0 = 0.f, z1 = 0.f, z2 = 0.f, z3 = 0.f;
            #pragma unroll
            for (int jj = 0; jj < 7; jj++) {
                int j = lane + 32*jj;
                if (j < NN) {
                    float e = __expf(sc[jj] - mx);
                    s += e;
                    float4 vv = *(const float4*)(vzs + j*4);
                    z0 = fmaf(e, vv.x, z0); z1 = fmaf(e, vv.y, z1);
                    z2 = fmaf(e, vv.z, z2); z3 = fmaf(e, vv.w, z3);
                }
            }
            #pragma unroll
            for (int off = 16; off; off >>= 1) {
                s  += __shfl_xor_sync(0xffffffffu, s,  off);
                z0 += __shfl_xor_sync(0xffffffffu, z0, off);
                z1 += __shfl_xor_sync(0xffffffffu, z1, off);
                z2 += __shfl_xor_sync(0xffffffffu, z2, off);
                z3 += __shfl_xor_sync(0xffffffffu, z3, off);
            }
            if (lane == 0) {
                float inv = 1.f / s;
                *(float4*)(g_zpart + ((size_t)bh*NN + (r0 + i))*4) =
                    make_float4(z0*inv, z1*inv, z2*inv, z3*inv);
            }
        }
    }
}

// ---------------- argmin + loss partial ----------------
__global__ void __launch_bounds__(256) argmin_kernel(const float* __restrict__ codebook,
                                                     const float* __restrict__ vq_in_b)
{
    __shared__ float4 cbs[DICN];
    __shared__ float  cns[DICN];
    __shared__ float  red[256];
    int tid = threadIdx.x;
    for (int c = tid; c < DICN; c += 256) {
        float4 e = *(const float4*)(codebook + c*4);
        cbs[c] = e;
        cns[c] = e.x*e.x + e.y*e.y + e.z*e.z + e.w*e.w;
    }
    __syncthreads();
    int p = blockIdx.x * 256 + tid;
    float lsum = 0.f;
    if (p < TOK) {
        int b = p / NN, n = p % NN;
        float z0 = vq_in_b[0], z1 = vq_in_b[1], z2 = vq_in_b[2], z3 = vq_in_b[3];
        #pragma unroll
        for (int h = 0; h < HH; h++) {
            float4 zp = *(const float4*)(g_zpart + (((size_t)b*HH + h)*NN + n)*4);
            z0 += zp.x; z1 += zp.y; z2 += zp.z; z3 += zp.w;
        }
        float best = 3.4e38f; int bi = 0;
        for (int c = 0; c < DICN; c++) {
            float4 e = cbs[c];
            float d = cns[c] - 2.f*(z0*e.x + z1*e.y + z2*e.z + z3*e.w);
            if (d < best) { best = d; bi = c; }
        }
        g_idx[p] = bi;
        float4 e = cbs[bi];
        float d0 = e.x - z0, d1 = e.y - z1, d2 = e.z - z2, d3 = e.w - z3;
        lsum = d0*d0 + d1*d1 + d2*d2 + d3*d3;
    }
    red[tid] = lsum;
    __syncthreads();
    for (int st = 128; st; st >>= 1) {
        if (tid < st) red[tid] += red[tid + st];
        __syncthreads();
    }
    if (tid == 0) g_losspart[blockIdx.x] = red[0];
}

__global__ void gather_out(const float* __restrict__ codebook, float* __restrict__ out)
{
    int p = blockIdx.x;
    int ci = g_idx[p];
    float4 e = *(const float4*)(codebook + ci*4);
    for (int o = threadIdx.x; o < CC; o += 256) {
        float4 pr = *(const float4*)(g_P + o*4);
        out[(size_t)p*CC + o] =
            fmaf(e.x, pr.x, fmaf(e.y, pr.y, fmaf(e.z, pr.z, fmaf(e.w, pr.w, g_b2[o]))));
    }
}

__global__ void loss_final(float* __restrict__ dst)
{
    float s = 0.f;
    for (int i = threadIdx.x; i < 50; i += 32) s += g_losspart[i];
    #pragma unroll
    for (int off = 16; off; off >>= 1) s += __shfl_xor_sync(0xffffffffu, s, off);
    if (threadIdx.x == 0) dst[0] = 1.25f * s / 50432.0f;
}

// ---------------- launch ----------------
extern "C" void kernel_launch(void* const* d_in, const int* in_sizes, int n_in,
                              void* d_out, int out_size)
{
    const float* x        = (const float*)d_in[0];
    const float* qkv_w    = (const float*)d_in[1];
    const float* proj_w   = (const float*)d_in[2];
    const float* proj_b   = (const float*)d_in[3];
    const float* vq_in_w  = (const float*)d_in[4];
    const float* vq_in_b  = (const float*)d_in[5];
    const float* vq_out_w = (const float*)d_in[6];
    const float* vq_out_b = (const float*)d_in[7];
    const float* codebook = (const float*)d_in[8];
    float* out = (float*)d_out;

    cudaFuncSetAttribute(attn_kernel, cudaFuncAttributeMaxDynamicSharedMemorySize, 110336);
    cudaFuncSetAttribute(qk_mma, cudaFuncAttributeMaxDynamicSharedMemorySize, 2*STAGE);

    __nv_bfloat16 *xh, *xl, *wh, *wl;
    cudaGetSymbolAddress((void**)&xh, g_xh);
    cudaGetSymbolAddress((void**)&xl, g_xl);
    cudaGetSymbolAddress((void**)&wh, g_wh);
    cudaGetSymbolAddress((void**)&wl, g_wl);

    conv_split<<<(TOK*CC/4 + 255)/256, 256>>>(x, xh, xl, TOK*CC/4);
    conv_split<<<(QKC*CC/4 + 255)/256, 256>>>(qkv_w, wh, wl, QKC*CC/4);
    prep_m<<<48, 256>>>(qkv_w, vq_in_w);
    prep_p<<<96, 256>>>(proj_w, proj_b, vq_out_w, vq_out_b);
    qk_mma<<<dim3(12, 99), 256, 2*STAGE>>>();
    vz_gemm<<<394, 256>>>(x);
    attn_kernel<<<BB*HH, 256, 110336>>>();
    argmin_kernel<<<50, 256>>>(codebook, vq_in_b);
    gather_out<<<TOK, 256>>>(codebook, out);
    loss_final<<<1, 32>>>(out + (size_t)out_size - 1);
}